// round 6
// baseline (speedup 1.0000x reference)
#include <cuda_runtime.h>
#include <cstdint>

// FWHT of 4096-wide rows, sign flip + 2^-6 normalization.
// Persistent CTAs (grid = 5*148), each grid-striding over rows with a
// single-buffer TMA pipeline: after the row is gathered into registers
// (and a CTA barrier), the NEXT row's cp.async.bulk is issued into the
// same shared buffer, overlapping the DMA with this row's compute+store.
// Signs are loaded once per CTA (loop-invariant).
//
// Butterfly structure (verified rounds 4/5, rel_err 1.2e-7):
//   Round 1: i = g*1024 + t*4 + c   regs {1,0,11,10} -> strides 1,2,1024,2048
//   Round 2: regs j = i[5:2]                         -> strides 4,8,16,32
//   Round 3: regs k = i[9:6]                         -> strides 64..512
// Exchange 1: pitch-20 rows keyed by reader (scalar STS imm / 4x LDS.128).
// Exchange 2: pitch-24 rows keyed by writer, quad slots XOR (t&4)
//             (4x STS.128 / scalar LDS imm, two bases).

#define FWHT_D 4096

__device__ __forceinline__ uint32_t smem_u32(const void* p)
{
    uint32_t a;
    asm("{ .reg .u64 tmp; cvta.to.shared.u64 tmp, %1; cvt.u32.u64 %0, tmp; }"
        : "=r"(a) : "l"(p));
    return a;
}

__device__ __forceinline__ void mbar_wait(uint32_t mb, uint32_t parity)
{
    uint32_t done;
    asm volatile(
        "{\n\t.reg .pred p;\n\t"
        "mbarrier.try_wait.parity.acquire.cta.shared::cta.b64 p, [%1], %2;\n\t"
        "selp.b32 %0, 1, 0, p;\n\t}"
        : "=r"(done) : "r"(mb), "r"(parity) : "memory");
    if (!done) {
        asm volatile(
            "{\n\t.reg .pred P1;\n\t"
            "WL_%=:\n\t"
            "mbarrier.try_wait.parity.acquire.cta.shared::cta.b64 P1, [%0], %1, 0x989680;\n\t"
            "@P1 bra.uni WD_%=;\n\t"
            "bra.uni WL_%=;\n\t"
            "WD_%=:\n\t}"
            :: "r"(mb), "r"(parity) : "memory");
    }
}

__device__ __forceinline__ void tma_row(uint32_t dst, const float* src, uint32_t mb)
{
    asm volatile("mbarrier.arrive.expect_tx.shared.b64 _, [%0], %1;"
                 :: "r"(mb), "r"((unsigned)(FWHT_D * 4)) : "memory");
    asm volatile(
        "cp.async.bulk.shared::cta.global.mbarrier::complete_tx::bytes "
        "[%0], [%1], %2, [%3];"
        :: "r"(dst), "l"(src), "r"((unsigned)(FWHT_D * 4)), "r"(mb)
        : "memory");
}

__device__ __forceinline__ void h16(float (&r)[16])
{
    #pragma unroll
    for (int p = 1; p < 16; p <<= 1) {
        #pragma unroll
        for (int k = 0; k < 16; ++k) {
            if ((k & p) == 0) {
                const float a = r[k];
                const float b = r[k | p];
                r[k]     = a + b;
                r[k | p] = a - b;
            }
        }
    }
}

__global__ __launch_bounds__(256, 5) void RHTRotation_82394652607202_kernel(
    const float* __restrict__ x,
    const float* __restrict__ signs,
    float* __restrict__ out,
    int rows)
{
    __shared__ __align__(128) float in_buf[FWHT_D];   // 16 KB TMA landing
    __shared__ __align__(128) float ex[6144];         // 24 KB exchange buffer
    __shared__ __align__(8)   uint64_t mbar;

    const int t = threadIdx.x;                         // 0..255
    const uint32_t mb  = smem_u32(&mbar);
    const uint32_t ibf = smem_u32(in_buf);

    // ---- loop-invariant: signs, pre-scaled by 4096^-0.5 ----
    const float scale = 0.015625f;
    float sc[16];
    #pragma unroll
    for (int g = 0; g < 4; ++g) {
        const float4 s = *reinterpret_cast<const float4*>(signs + g * 1024 + t * 4);
        sc[g * 4 + 0] = s.x * scale;
        sc[g * 4 + 1] = s.y * scale;
        sc[g * 4 + 2] = s.z * scale;
        sc[g * 4 + 3] = s.w * scale;
    }

    if (t == 0) {
        asm volatile("mbarrier.init.shared.b64 [%0], %1;" :: "r"(mb), "r"(1));
        asm volatile("fence.proxy.async.shared::cta;" ::: "memory");
    }
    __syncthreads();

    int row = blockIdx.x;
    if (row < rows && t == 0)
        tma_row(ibf, x + (long long)row * FWHT_D, mb);

    uint32_t parity = 0;
    const int stride = gridDim.x;

    for (; row < rows; row += stride) {
        // ---- wait for this row's DMA ----
        mbar_wait(mb, parity);
        parity ^= 1;

        // ---- gather row into registers (4x LDS.128, conflict-free) ----
        float r[16];
        #pragma unroll
        for (int g = 0; g < 4; ++g) {
            const float4 v = *reinterpret_cast<const float4*>(in_buf + g * 1024 + t * 4);
            r[g * 4 + 0] = v.x * sc[g * 4 + 0];
            r[g * 4 + 1] = v.y * sc[g * 4 + 1];
            r[g * 4 + 2] = v.z * sc[g * 4 + 2];
            r[g * 4 + 3] = v.w * sc[g * 4 + 3];
        }
        __syncthreads();          // everyone done reading in_buf

        // ---- prefetch the NEXT row into the same buffer (overlaps compute) ----
        const int next = row + stride;
        if (next < rows && t == 0)
            tma_row(ibf, x + (long long)next * FWHT_D, mb);

        // ---- round 1: strides 1,2,1024,2048 ----
        h16(r);

        // ---- exchange 1 write: addr = g*1280 + (t>>4)*80 + c*20 + (t&15) ----
        {
            const int base = (t >> 4) * 80 + (t & 15);
            #pragma unroll
            for (int g = 0; g < 4; ++g)
                #pragma unroll
                for (int c = 0; c < 4; ++c)
                    ex[base + g * 1280 + c * 20] = r[g * 4 + c];
        }
        __syncthreads();

        // ---- exchange 1 read: row t, 4x LDS.128 ----
        {
            const float* rp = ex + t * 20;
            #pragma unroll
            for (int q = 0; q < 4; ++q) {
                const float4 v = *reinterpret_cast<const float4*>(rp + 4 * q);
                r[q * 4 + 0] = v.x; r[q * 4 + 1] = v.y;
                r[q * 4 + 2] = v.z; r[q * 4 + 3] = v.w;
            }
        }

        // ---- round 2: strides 4,8,16,32 ----
        h16(r);

        __syncthreads();          // ex buffer reuse

        // ---- exchange 2 write: row t, pitch 24, quad slot (4q ^ (t&4)) ----
        {
            const int c4 = t & 4;
            float* wp = ex + t * 24;
            #pragma unroll
            for (int q = 0; q < 4; ++q) {
                *reinterpret_cast<float4*>(wp + ((4 * q) ^ c4)) =
                    make_float4(r[q * 4 + 0], r[q * 4 + 1], r[q * 4 + 2], r[q * 4 + 3]);
            }
        }
        __syncthreads();

        // ---- exchange 2 read: addr = A + k*96 + (B or B^4) ----
        {
            const int A  = (t >> 6) * 1536 + (t & 3) * 24;
            const int B  = (t >> 2) & 15;
            const int be = A + B;
            const int bo = A + (B ^ 4);
            #pragma unroll
            for (int k = 0; k < 16; ++k)
                r[k] = ex[((k & 1) ? bo : be) + k * 96];
        }

        // ---- round 3: strides 64,128,256,512 ----
        h16(r);

        // ---- store: i = (t>>6)*1024 + k*64 + (t&63), 128B/instr ----
        {
            float* op = out + (long long)row * FWHT_D + (t >> 6) * 1024 + (t & 63);
            #pragma unroll
            for (int k = 0; k < 16; ++k)
                op[k * 64] = r[k];
        }
        // Next iteration's first action is mbar_wait; ex rewrite is guarded
        // by the post-gather __syncthreads of that iteration.
    }
}

extern "C" void kernel_launch(void* const* d_in, const int* in_sizes, int n_in,
                              void* d_out, int out_size)
{
    const float* a = (const float*)d_in[0];
    const float* b = (const float*)d_in[1];
    const float* x;
    const float* signs;
    if (in_sizes[0] == FWHT_D && in_sizes[1] > FWHT_D) { signs = a; x = b; }
    else                                               { x = a; signs = b; }

    const int rows = out_size / FWHT_D;
    int grid = 5 * 148;                 // 5 CTAs/SM, persistent
    if (grid > rows) grid = rows;
    RHTRotation_82394652607202_kernel<<<grid, 256>>>(x, signs, (float*)d_out, rows);
}

// round 7
// speedup vs baseline: 1.1007x; 1.1007x over previous
#include <cuda_runtime.h>
#include <cstdint>

// FWHT of 4096-wide rows, sign flip + 2^-6 normalization.
// Persistent CTAs (grid = 5*148) with DYNAMIC row scheduling via a global
// atomic counter (self-balancing — fixes the static-partition straggler tail
// seen in round 6), single-buffer TMA pipeline: after the current row is
// gathered into registers, the next row index is drawn and its cp.async.bulk
// issued into the same buffer, overlapping DMA with compute+store.
//
// Butterfly structure (verified, rel_err 1.2e-7):
//   Round 1: i = g*1024 + t*4 + c   regs {1,0,11,10} -> strides 1,2,1024,2048
//   Round 2: regs j = i[5:2]                         -> strides 4,8,16,32
//   Round 3: regs k = i[9:6]                         -> strides 64..512
// Exchange 1: pitch-20 rows keyed by reader (scalar STS imm / 4x LDS.128).
// Exchange 2: pitch-24 rows keyed by writer, quad slots XOR (t&4)
//             (4x STS.128 / scalar LDS imm, two bases).

#define FWHT_D 4096

__device__ int g_row_ctr;

__device__ __forceinline__ uint32_t smem_u32(const void* p)
{
    uint32_t a;
    asm("{ .reg .u64 tmp; cvta.to.shared.u64 tmp, %1; cvt.u32.u64 %0, tmp; }"
        : "=r"(a) : "l"(p));
    return a;
}

__device__ __forceinline__ void mbar_wait(uint32_t mb, uint32_t parity)
{
    uint32_t done;
    asm volatile(
        "{\n\t.reg .pred p;\n\t"
        "mbarrier.try_wait.parity.acquire.cta.shared::cta.b64 p, [%1], %2;\n\t"
        "selp.b32 %0, 1, 0, p;\n\t}"
        : "=r"(done) : "r"(mb), "r"(parity) : "memory");
    if (!done) {
        asm volatile(
            "{\n\t.reg .pred P1;\n\t"
            "WL_%=:\n\t"
            "mbarrier.try_wait.parity.acquire.cta.shared::cta.b64 P1, [%0], %1, 0x989680;\n\t"
            "@P1 bra.uni WD_%=;\n\t"
            "bra.uni WL_%=;\n\t"
            "WD_%=:\n\t}"
            :: "r"(mb), "r"(parity) : "memory");
    }
}

__device__ __forceinline__ void tma_row(uint32_t dst, const float* src, uint32_t mb)
{
    asm volatile("mbarrier.arrive.expect_tx.shared.b64 _, [%0], %1;"
                 :: "r"(mb), "r"((unsigned)(FWHT_D * 4)) : "memory");
    asm volatile(
        "cp.async.bulk.shared::cta.global.mbarrier::complete_tx::bytes "
        "[%0], [%1], %2, [%3];"
        :: "r"(dst), "l"(src), "r"((unsigned)(FWHT_D * 4)), "r"(mb)
        : "memory");
}

__device__ __forceinline__ void h16(float (&r)[16])
{
    #pragma unroll
    for (int p = 1; p < 16; p <<= 1) {
        #pragma unroll
        for (int k = 0; k < 16; ++k) {
            if ((k & p) == 0) {
                const float a = r[k];
                const float b = r[k | p];
                r[k]     = a + b;
                r[k | p] = a - b;
            }
        }
    }
}

__global__ __launch_bounds__(256, 5) void RHTRotation_82394652607202_kernel(
    const float* __restrict__ x,
    const float* __restrict__ signs,
    float* __restrict__ out,
    int rows)
{
    __shared__ __align__(128) float in_buf[FWHT_D];   // 16 KB TMA landing
    __shared__ __align__(128) float ex[6144];         // 24 KB exchange buffer
    __shared__ __align__(8)   uint64_t mbar;
    __shared__ int sh_row;

    const int t = threadIdx.x;                         // 0..255
    const uint32_t mb  = smem_u32(&mbar);
    const uint32_t ibf = smem_u32(in_buf);

    // ---- prologue: init mbar, draw first row, launch its DMA ASAP ----
    if (t == 0) {
        asm volatile("mbarrier.init.shared.b64 [%0], %1;" :: "r"(mb), "r"(1));
        asm volatile("fence.proxy.async.shared::cta;" ::: "memory");
    }
    __syncthreads();
    if (t == 0) {
        const int r0 = atomicAdd(&g_row_ctr, 1);
        sh_row = r0;
        if (r0 < rows)
            tma_row(ibf, x + (long long)r0 * FWHT_D, mb);
    }

    // ---- loop-invariant: signs * 4096^-0.5 (overlaps first DMA) ----
    const float scale = 0.015625f;
    float sc[16];
    #pragma unroll
    for (int g = 0; g < 4; ++g) {
        const float4 s = *reinterpret_cast<const float4*>(signs + g * 1024 + t * 4);
        sc[g * 4 + 0] = s.x * scale;
        sc[g * 4 + 1] = s.y * scale;
        sc[g * 4 + 2] = s.z * scale;
        sc[g * 4 + 3] = s.w * scale;
    }

    __syncthreads();                       // publish sh_row
    int cur = sh_row;

    uint32_t parity = 0;

    while (cur < rows) {
        // ---- wait for this row's DMA ----
        mbar_wait(mb, parity);
        parity ^= 1;

        // ---- gather row into registers (4x LDS.128, conflict-free) ----
        float r[16];
        #pragma unroll
        for (int g = 0; g < 4; ++g) {
            const float4 v = *reinterpret_cast<const float4*>(in_buf + g * 1024 + t * 4);
            r[g * 4 + 0] = v.x * sc[g * 4 + 0];
            r[g * 4 + 1] = v.y * sc[g * 4 + 1];
            r[g * 4 + 2] = v.z * sc[g * 4 + 2];
            r[g * 4 + 3] = v.w * sc[g * 4 + 3];
        }
        __syncthreads();          // everyone done reading in_buf

        // ---- draw next row, prefetch into the same buffer (overlaps compute) ----
        if (t == 0) {
            const int nxt = atomicAdd(&g_row_ctr, 1);
            sh_row = nxt;
            if (nxt < rows)
                tma_row(ibf, x + (long long)nxt * FWHT_D, mb);
        }

        // ---- round 1: strides 1,2,1024,2048 ----
        h16(r);

        // ---- exchange 1 write: addr = g*1280 + (t>>4)*80 + c*20 + (t&15) ----
        {
            const int base = (t >> 4) * 80 + (t & 15);
            #pragma unroll
            for (int g = 0; g < 4; ++g)
                #pragma unroll
                for (int c = 0; c < 4; ++c)
                    ex[base + g * 1280 + c * 20] = r[g * 4 + c];
        }
        __syncthreads();          // also publishes sh_row (t0 wrote it above)

        const int nxt_row = sh_row;

        // ---- exchange 1 read: row t, 4x LDS.128 ----
        {
            const float* rp = ex + t * 20;
            #pragma unroll
            for (int q = 0; q < 4; ++q) {
                const float4 v = *reinterpret_cast<const float4*>(rp + 4 * q);
                r[q * 4 + 0] = v.x; r[q * 4 + 1] = v.y;
                r[q * 4 + 2] = v.z; r[q * 4 + 3] = v.w;
            }
        }

        // ---- round 2: strides 4,8,16,32 ----
        h16(r);

        __syncthreads();          // ex buffer reuse

        // ---- exchange 2 write: row t, pitch 24, quad slot (4q ^ (t&4)) ----
        {
            const int c4 = t & 4;
            float* wp = ex + t * 24;
            #pragma unroll
            for (int q = 0; q < 4; ++q) {
                *reinterpret_cast<float4*>(wp + ((4 * q) ^ c4)) =
                    make_float4(r[q * 4 + 0], r[q * 4 + 1], r[q * 4 + 2], r[q * 4 + 3]);
            }
        }
        __syncthreads();

        // ---- exchange 2 read: addr = A + k*96 + (B or B^4) ----
        {
            const int A  = (t >> 6) * 1536 + (t & 3) * 24;
            const int B  = (t >> 2) & 15;
            const int be = A + B;
            const int bo = A + (B ^ 4);
            #pragma unroll
            for (int k = 0; k < 16; ++k)
                r[k] = ex[((k & 1) ? bo : be) + k * 96];
        }

        // ---- round 3: strides 64,128,256,512 ----
        h16(r);

        // ---- store: i = (t>>6)*1024 + k*64 + (t&63), 128B/instr ----
        {
            float* op = out + (long long)cur * FWHT_D + (t >> 6) * 1024 + (t & 63);
            #pragma unroll
            for (int k = 0; k < 16; ++k)
                op[k * 64] = r[k];
        }

        cur = nxt_row;
        // Next iteration's mbar_wait pairs with the release arrive of the
        // prefetch; ex rewrite is guarded by that iteration's gather sync.
    }
}

extern "C" void kernel_launch(void* const* d_in, const int* in_sizes, int n_in,
                              void* d_out, int out_size)
{
    const float* a = (const float*)d_in[0];
    const float* b = (const float*)d_in[1];
    const float* x;
    const float* signs;
    if (in_sizes[0] == FWHT_D && in_sizes[1] > FWHT_D) { signs = a; x = b; }
    else                                               { x = a; signs = b; }

    const int rows = out_size / FWHT_D;

    // Reset the dynamic-scheduling counter (graph-capturable async memset).
    void* ctr_addr = nullptr;
    cudaGetSymbolAddress(&ctr_addr, g_row_ctr);
    cudaMemsetAsync(ctr_addr, 0, sizeof(int));

    int grid = 5 * 148;                 // 5 CTAs/SM, persistent, work-stealing
    if (grid > rows) grid = rows;
    RHTRotation_82394652607202_kernel<<<grid, 256>>>(x, signs, (float*)d_out, rows);
}